// round 1
// baseline (speedup 1.0000x reference)
#include <cuda_runtime.h>
#include <math.h>

// ---------------------------------------------------------------------------
// GPT block: B=4, S=2048, D_MODEL=1024, H=16, DK=64, DFF=4096, fp32, causal.
// Round-1 baseline: fp32 FFMA SGEMM + flash-attention + fused epilogues.
// ---------------------------------------------------------------------------

#define BATCH  4
#define SEQ    2048
#define DMODEL 1024
#define NHEAD  16
#define DHEAD  64
#define DFF    4096
#define MROWS  (BATCH * SEQ)   // 8192

// Scratch (device globals: allocation-free per harness rules)
__device__ float g_Q[MROWS * DMODEL];           // [B,H,S,DK]
__device__ float g_K[MROWS * DMODEL];           // [B,H,S,DK]
__device__ float g_V[MROWS * DMODEL];           // [B,H,S,DK]
__device__ float g_ctx[MROWS * DMODEL];         // [M, DMODEL] (head-interleaved back)
__device__ float g_res1[MROWS * DMODEL];        // x + attn_out
__device__ float g_h[MROWS * DMODEL];           // LN1 output
__device__ float g_ff[(long long)MROWS * DFF];  // gelu(h@w1^T+b1)
__device__ float g_res2[MROWS * DMODEL];        // h + ff_out

// ---------------------------------------------------------------------------
// SGEMM: C = A[M,K] @ W[N,K]^T (+ bias) with epilogue modes.
// BM=BN=128, BK=8, 256 threads, 8x8 micro-tile per thread.
// MODE 1: QKV   -> scatter to [B,H,S,DK] layout, +bias
// MODE 2: ADD   -> +bias +residual add[m*N+n], row-major store
// MODE 3: GELU  -> +bias, exact gelu, row-major store
// ---------------------------------------------------------------------------
template <int MODE>
__global__ void __launch_bounds__(256) sgemm_kernel(
    const float* __restrict__ A, const float* __restrict__ W,
    const float* __restrict__ bias, const float* __restrict__ add,
    float* __restrict__ C, int Ndim, int Kdim)
{
    __shared__ float As[8][128];
    __shared__ float Bs[8][128];

    const int tid = threadIdx.x;
    const int m0 = blockIdx.y * 128;
    const int n0 = blockIdx.x * 128;
    const int tx = tid & 15;       // 0..15 -> n micro
    const int ty = tid >> 4;       // 0..15 -> m micro

    const int lrow = tid >> 1;          // 0..127
    const int lcol = (tid & 1) * 4;     // 0 or 4

    const float* Aptr = A + (size_t)(m0 + lrow) * Kdim + lcol;
    const float* Wptr = W + (size_t)(n0 + lrow) * Kdim + lcol;

    float c[8][8];
#pragma unroll
    for (int i = 0; i < 8; i++)
#pragma unroll
        for (int j = 0; j < 8; j++) c[i][j] = 0.0f;

    for (int kt = 0; kt < Kdim; kt += 8) {
        float4 a = *(const float4*)Aptr;
        float4 b = *(const float4*)Wptr;
        Aptr += 8; Wptr += 8;

        __syncthreads();
        As[lcol + 0][lrow] = a.x; As[lcol + 1][lrow] = a.y;
        As[lcol + 2][lrow] = a.z; As[lcol + 3][lrow] = a.w;
        Bs[lcol + 0][lrow] = b.x; Bs[lcol + 1][lrow] = b.y;
        Bs[lcol + 2][lrow] = b.z; Bs[lcol + 3][lrow] = b.w;
        __syncthreads();

#pragma unroll
        for (int k = 0; k < 8; k++) {
            float av[8], bv[8];
            *(float4*)(av)     = *(const float4*)&As[k][ty * 8];
            *(float4*)(av + 4) = *(const float4*)&As[k][ty * 8 + 4];
            *(float4*)(bv)     = *(const float4*)&Bs[k][tx * 8];
            *(float4*)(bv + 4) = *(const float4*)&Bs[k][tx * 8 + 4];
#pragma unroll
            for (int i = 0; i < 8; i++)
#pragma unroll
                for (int j = 0; j < 8; j++)
                    c[i][j] = fmaf(av[i], bv[j], c[i][j]);
        }
    }

#pragma unroll
    for (int i = 0; i < 8; i++) {
        const int m = m0 + ty * 8 + i;
#pragma unroll
        for (int j = 0; j < 8; j++) {
            const int n = n0 + tx * 8 + j;
            float v = c[i][j] + bias[n];
            if (MODE == 1) {
                const int b  = m >> 11;         // m / SEQ
                const int s  = m & (SEQ - 1);
                const int hh = n >> 6;          // n / DHEAD
                const int dk = n & (DHEAD - 1);
                C[(((size_t)(b * NHEAD + hh)) * SEQ + s) * DHEAD + dk] = v;
            } else if (MODE == 2) {
                C[(size_t)m * Ndim + n] = v + add[(size_t)m * Ndim + n];
            } else { // MODE == 3
                C[(size_t)m * Ndim + n] = 0.5f * v * (1.0f + erff(v * 0.70710678118654752f));
            }
        }
    }
}

// ---------------------------------------------------------------------------
// Flash attention (fp32): one block per (b, h, q-tile of 64 rows).
// Static 48 KB smem: Qs(16K) + KPs(16K, K-tile reused for P) + Vs(16K).
// 256 threads; thread (ty,tx) owns q rows ty*4..+3, d/k cols tx*4..+3.
// ---------------------------------------------------------------------------
__global__ void __launch_bounds__(256) attn_kernel(
    const float* __restrict__ Qg, const float* __restrict__ Kg,
    const float* __restrict__ Vg, float* __restrict__ ctx)
{
    __shared__ float Qs[64 * 64];
    __shared__ float KPs[64 * 64];   // K tile, reused as P tile
    __shared__ float Vs[64 * 64];

    const int tid = threadIdx.x;
    const int qt = blockIdx.x;        // q tile (0..31)
    const int hh = blockIdx.y;
    const int bb = blockIdx.z;
    const int tx = tid & 15;
    const int ty = tid >> 4;

    const size_t headbase = (size_t)(bb * NHEAD + hh) * SEQ * DHEAD;
    const float* Qhead = Qg + headbase + (size_t)qt * 64 * DHEAD;
    const float* Khead = Kg + headbase;
    const float* Vhead = Vg + headbase;

    // Load Q tile, pre-scaled by 1/sqrt(64)
    const float scale = 0.125f;
#pragma unroll
    for (int i = 0; i < 4; i++) {
        int idx = tid + i * 256;          // float4 index 0..1023
        float4 q = ((const float4*)Qhead)[idx];
        q.x *= scale; q.y *= scale; q.z *= scale; q.w *= scale;
        ((float4*)Qs)[idx] = q;
    }

    float acc[4][4];
    float mi[4], li[4];
#pragma unroll
    for (int i = 0; i < 4; i++) {
        mi[i] = -1e30f; li[i] = 0.0f;
#pragma unroll
        for (int j = 0; j < 4; j++) acc[i][j] = 0.0f;
    }

    for (int kt = 0; kt <= qt; kt++) {
        __syncthreads();   // protect KPs/Vs from previous iteration readers (and Qs writes)
#pragma unroll
        for (int i = 0; i < 4; i++) {
            int idx = tid + i * 256;
            ((float4*)KPs)[idx] = ((const float4*)(Khead + (size_t)kt * 64 * DHEAD))[idx];
            ((float4*)Vs)[idx]  = ((const float4*)(Vhead + (size_t)kt * 64 * DHEAD))[idx];
        }
        __syncthreads();

        // Phase A: S = Q K^T (scaled)
        float s[4][4];
#pragma unroll
        for (int i = 0; i < 4; i++)
#pragma unroll
            for (int j = 0; j < 4; j++) s[i][j] = 0.0f;

#pragma unroll 4
        for (int d4 = 0; d4 < 16; d4++) {
            float4 q4[4], k4[4];
#pragma unroll
            for (int i = 0; i < 4; i++) q4[i] = ((const float4*)Qs)[(ty * 4 + i) * 16 + d4];
#pragma unroll
            for (int j = 0; j < 4; j++) k4[j] = ((const float4*)KPs)[(tx * 4 + j) * 16 + d4];
#pragma unroll
            for (int i = 0; i < 4; i++)
#pragma unroll
                for (int j = 0; j < 4; j++) {
                    s[i][j] = fmaf(q4[i].x, k4[j].x, s[i][j]);
                    s[i][j] = fmaf(q4[i].y, k4[j].y, s[i][j]);
                    s[i][j] = fmaf(q4[i].z, k4[j].z, s[i][j]);
                    s[i][j] = fmaf(q4[i].w, k4[j].w, s[i][j]);
                }
        }

        if (kt == qt) {   // diagonal tile: apply causal mask
#pragma unroll
            for (int i = 0; i < 4; i++)
#pragma unroll
                for (int j = 0; j < 4; j++)
                    if (tx * 4 + j > ty * 4 + i) s[i][j] = -1e30f;
        }

        __syncthreads();  // everyone done reading K from KPs before P overwrite

        // Phase B: online softmax, write P into KPs
#pragma unroll
        for (int i = 0; i < 4; i++) {
            float lm = fmaxf(fmaxf(s[i][0], s[i][1]), fmaxf(s[i][2], s[i][3]));
#pragma unroll
            for (int off = 1; off < 16; off <<= 1)
                lm = fmaxf(lm, __shfl_xor_sync(0xffffffffu, lm, off));
            float mnew = fmaxf(mi[i], lm);
            float corr = __expf(mi[i] - mnew);
            mi[i] = mnew;
            float rs = 0.0f;
#pragma unroll
            for (int j = 0; j < 4; j++) {
                float p = __expf(s[i][j] - mnew);
                KPs[(ty * 4 + i) * 64 + tx * 4 + j] = p;
                rs += p;
            }
#pragma unroll
            for (int off = 1; off < 16; off <<= 1)
                rs += __shfl_xor_sync(0xffffffffu, rs, off);
            li[i] = li[i] * corr + rs;
#pragma unroll
            for (int dc = 0; dc < 4; dc++) acc[i][dc] *= corr;
        }
        __syncthreads();

        // Phase C: O += P @ V
#pragma unroll 4
        for (int k4 = 0; k4 < 16; k4++) {
            float4 p4[4];
#pragma unroll
            for (int i = 0; i < 4; i++) p4[i] = ((const float4*)KPs)[(ty * 4 + i) * 16 + k4];
#pragma unroll
            for (int kk = 0; kk < 4; kk++) {
                float4 v4 = ((const float4*)Vs)[(k4 * 4 + kk) * 16 + tx];
#pragma unroll
                for (int i = 0; i < 4; i++) {
                    float p = (kk == 0) ? p4[i].x : (kk == 1) ? p4[i].y : (kk == 2) ? p4[i].z : p4[i].w;
                    acc[i][0] = fmaf(p, v4.x, acc[i][0]);
                    acc[i][1] = fmaf(p, v4.y, acc[i][1]);
                    acc[i][2] = fmaf(p, v4.z, acc[i][2]);
                    acc[i][3] = fmaf(p, v4.w, acc[i][3]);
                }
            }
        }
    }

    // Write ctx in [B,S, H*DK] layout for the O-projection GEMM
#pragma unroll
    for (int i = 0; i < 4; i++) {
        const float inv = 1.0f / li[i];
        const int qg = qt * 64 + ty * 4 + i;
        float4 o;
        o.x = acc[i][0] * inv; o.y = acc[i][1] * inv;
        o.z = acc[i][2] * inv; o.w = acc[i][3] * inv;
        *(float4*)&ctx[((size_t)bb * SEQ + qg) * DMODEL + hh * DHEAD + tx * 4] = o;
    }
}

// ---------------------------------------------------------------------------
// LayerNorm: one block per row, 256 threads, float4 per thread (1024 cols).
// ---------------------------------------------------------------------------
__global__ void __launch_bounds__(256) ln_kernel(
    const float* __restrict__ in, const float* __restrict__ sc,
    const float* __restrict__ bi, float* __restrict__ out)
{
    __shared__ float red0[8], red1[8];
    __shared__ float s_mu, s_inv;
    const int row = blockIdx.x;
    const int tid = threadIdx.x;

    float4 x = ((const float4*)(in + (size_t)row * DMODEL))[tid];
    float sum = x.x + x.y + x.z + x.w;
    float sq  = x.x * x.x + x.y * x.y + x.z * x.z + x.w * x.w;
#pragma unroll
    for (int o = 16; o; o >>= 1) {
        sum += __shfl_xor_sync(0xffffffffu, sum, o);
        sq  += __shfl_xor_sync(0xffffffffu, sq, o);
    }
    if ((tid & 31) == 0) { red0[tid >> 5] = sum; red1[tid >> 5] = sq; }
    __syncthreads();
    if (tid < 32) {
        float s = (tid < 8) ? red0[tid] : 0.0f;
        float q = (tid < 8) ? red1[tid] : 0.0f;
#pragma unroll
        for (int o = 4; o; o >>= 1) {
            s += __shfl_xor_sync(0xffffffffu, s, o);
            q += __shfl_xor_sync(0xffffffffu, q, o);
        }
        if (tid == 0) {
            float mu = s * (1.0f / DMODEL);
            float var = q * (1.0f / DMODEL) - mu * mu;
            s_mu = mu;
            s_inv = rsqrtf(var + 1e-5f);
        }
    }
    __syncthreads();
    const float mu = s_mu, inv = s_inv;
    float4 g = ((const float4*)sc)[tid];
    float4 b = ((const float4*)bi)[tid];
    float4 o;
    o.x = (x.x - mu) * inv * g.x + b.x;
    o.y = (x.y - mu) * inv * g.y + b.y;
    o.z = (x.z - mu) * inv * g.z + b.z;
    o.w = (x.w - mu) * inv * g.w + b.w;
    ((float4*)(out + (size_t)row * DMODEL))[tid] = o;
}

// ---------------------------------------------------------------------------
extern "C" void kernel_launch(void* const* d_in, const int* in_sizes, int n_in,
                              void* d_out, int out_size)
{
    (void)in_sizes; (void)n_in; (void)out_size;
    const float* x    = (const float*)d_in[0];
    // d_in[1] = causal mask (derived analytically; unused)
    const float* wq   = (const float*)d_in[2];
    const float* bq   = (const float*)d_in[3];
    const float* wk   = (const float*)d_in[4];
    const float* bk   = (const float*)d_in[5];
    const float* wv   = (const float*)d_in[6];
    const float* bv   = (const float*)d_in[7];
    const float* wo   = (const float*)d_in[8];
    const float* bo   = (const float*)d_in[9];
    const float* w1   = (const float*)d_in[10];
    const float* b1   = (const float*)d_in[11];
    const float* w2   = (const float*)d_in[12];
    const float* b2   = (const float*)d_in[13];
    const float* ln1s = (const float*)d_in[14];
    const float* ln1b = (const float*)d_in[15];
    const float* ln2s = (const float*)d_in[16];
    const float* ln2b = (const float*)d_in[17];
    float* out = (float*)d_out;

    float *Q, *K, *V, *ctx, *res1, *h, *ff, *res2;
    cudaGetSymbolAddress((void**)&Q,    g_Q);
    cudaGetSymbolAddress((void**)&K,    g_K);
    cudaGetSymbolAddress((void**)&V,    g_V);
    cudaGetSymbolAddress((void**)&ctx,  g_ctx);
    cudaGetSymbolAddress((void**)&res1, g_res1);
    cudaGetSymbolAddress((void**)&h,    g_h);
    cudaGetSymbolAddress((void**)&ff,   g_ff);
    cudaGetSymbolAddress((void**)&res2, g_res2);

    const dim3 blk(256);
    const dim3 grid_dm(DMODEL / 128, MROWS / 128);   // (8, 64)
    const dim3 grid_ff(DFF / 128,   MROWS / 128);    // (32, 64)

    // QKV projections -> [B,H,S,DK]
    sgemm_kernel<1><<<grid_dm, blk>>>(x, wq, bq, nullptr, Q, DMODEL, DMODEL);
    sgemm_kernel<1><<<grid_dm, blk>>>(x, wk, bk, nullptr, K, DMODEL, DMODEL);
    sgemm_kernel<1><<<grid_dm, blk>>>(x, wv, bv, nullptr, V, DMODEL, DMODEL);

    // Causal flash attention -> ctx [B,S,DMODEL]
    attn_kernel<<<dim3(SEQ / 64, NHEAD, BATCH), blk>>>(Q, K, V, ctx);

    // O projection + residual(x) -> res1; LN1 -> h
    sgemm_kernel<2><<<grid_dm, blk>>>(ctx, wo, bo, x, res1, DMODEL, DMODEL);
    ln_kernel<<<MROWS, blk>>>(res1, ln1s, ln1b, h);

    // FFN1 + exact GELU -> ff
    sgemm_kernel<3><<<grid_ff, blk>>>(h, w1, b1, nullptr, ff, DFF, DMODEL);

    // FFN2 + residual(h) -> res2; LN2 -> out
    sgemm_kernel<2><<<grid_dm, blk>>>(ff, w2, b2, h, res2, DMODEL, DFF);
    ln_kernel<<<MROWS, blk>>>(res2, ln2s, ln2b, out);
}

// round 3
// speedup vs baseline: 1.8023x; 1.8023x over previous
#include <cuda_runtime.h>
#include <cuda_bf16.h>
#include <math.h>
#include <stdint.h>

// ---------------------------------------------------------------------------
// GPT block: B=4, S=2048, D_MODEL=1024, H=16, DK=64, DFF=4096, fp32, causal.
// Round-3: GEMMs on HMMA via mma.sync bf16 (bf16x3 split), cp.async.bulk pipe.
// (tcgen05 PTX is unavailable: harness targets sm_103 base, not sm_103a.)
// ---------------------------------------------------------------------------

#define BATCH  4
#define SEQ    2048
#define DMODEL 1024
#define NHEAD  16
#define DHEAD  64
#define DFF    4096
#define MROWS  (BATCH * SEQ)   // 8192
#define MBTOT  (MROWS / 128)   // 64

// ---------------- fp32 scratch ----------------
__device__ float g_Q[MROWS * DMODEL];
__device__ float g_K[MROWS * DMODEL];
__device__ float g_V[MROWS * DMODEL];
__device__ float g_ctx[MROWS * DMODEL];
__device__ float g_res1[MROWS * DMODEL];
__device__ float g_h[MROWS * DMODEL];
__device__ float g_ff[(size_t)MROWS * DFF];
__device__ float g_res2[MROWS * DMODEL];
__device__ float g_bqkv[3 * DMODEL];

// ---------------- bf16 hi/lo chunked (pre-swizzled SW128) scratch ----------
// layout: [KC][RB][128 rows][64 cols] bf16, each 128x64 block = 16KB
__device__ __align__(1024) __nv_bfloat16 g_x2hi[MROWS * DMODEL];
__device__ __align__(1024) __nv_bfloat16 g_x2lo[MROWS * DMODEL];
__device__ __align__(1024) __nv_bfloat16 g_ctx2hi[MROWS * DMODEL];
__device__ __align__(1024) __nv_bfloat16 g_ctx2lo[MROWS * DMODEL];
__device__ __align__(1024) __nv_bfloat16 g_h2hi[MROWS * DMODEL];
__device__ __align__(1024) __nv_bfloat16 g_h2lo[MROWS * DMODEL];
__device__ __align__(1024) __nv_bfloat16 g_ff2hi[(size_t)MROWS * DFF];
__device__ __align__(1024) __nv_bfloat16 g_ff2lo[(size_t)MROWS * DFF];
__device__ __align__(1024) __nv_bfloat16 g_wqkvhi[3 * DMODEL * DMODEL];
__device__ __align__(1024) __nv_bfloat16 g_wqkvlo[3 * DMODEL * DMODEL];
__device__ __align__(1024) __nv_bfloat16 g_wohi[DMODEL * DMODEL];
__device__ __align__(1024) __nv_bfloat16 g_wolo[DMODEL * DMODEL];
__device__ __align__(1024) __nv_bfloat16 g_w1hi[DFF * DMODEL];
__device__ __align__(1024) __nv_bfloat16 g_w1lo[DFF * DMODEL];
__device__ __align__(1024) __nv_bfloat16 g_w2hi[DMODEL * DFF];
__device__ __align__(1024) __nv_bfloat16 g_w2lo[DMODEL * DFF];

// ---------------------------------------------------------------------------
// PTX helpers (base-target only: mbarrier, cp.async.bulk, ldmatrix, mma.sync)
// ---------------------------------------------------------------------------
__device__ __forceinline__ uint32_t smem_u32(const void* p) {
    uint32_t a;
    asm("{ .reg .u64 t; cvta.to.shared.u64 t, %1; cvt.u32.u64 %0, t; }" : "=r"(a) : "l"(p));
    return a;
}

#define MBARRIER_INIT(addr, cnt) \
    asm volatile("mbarrier.init.shared.b64 [%0], %1;" :: "r"((uint32_t)(addr)), "r"((uint32_t)(cnt)) : "memory")

#define MBARRIER_EXPECT_TX(addr, bytes) \
    asm volatile("mbarrier.arrive.expect_tx.shared.b64 _, [%0], %1;" :: "r"((uint32_t)(addr)), "r"((uint32_t)(bytes)) : "memory")

#define MBARRIER_WAIT_PARITY(mbar_smem_addr, phase_parity) do { \
    uint32_t _mbar = (uint32_t)(mbar_smem_addr); \
    uint32_t _parity = (uint32_t)(phase_parity); \
    uint32_t _done; \
    asm volatile( \
        "{\n\t.reg .pred p;\n\t" \
        "mbarrier.try_wait.parity.acquire.cta.shared::cta.b64 p, [%1], %2;\n\t" \
        "selp.b32 %0, 1, 0, p;\n\t}" \
        : "=r"(_done) : "r"(_mbar), "r"(_parity) : "memory"); \
    if (!_done) { \
        asm volatile( \
            "{\n\t.reg .pred P1;\n\t" \
            "WAIT_LOOP_%=:\n\t" \
            "mbarrier.try_wait.parity.acquire.cta.shared::cta.b64 P1, [%0], %1, 0x989680;\n\t" \
            "@P1 bra.uni WAIT_DONE_%=;\n\t" \
            "bra.uni WAIT_LOOP_%=;\n\t" \
            "WAIT_DONE_%=:\n\t}" \
            :: "r"(_mbar), "r"(_parity) : "memory"); \
    } \
} while(0)

__device__ __forceinline__ void bulk_g2s(uint32_t dst, const void* src, uint32_t bytes, uint32_t mbar) {
    asm volatile(
        "cp.async.bulk.shared::cluster.global.mbarrier::complete_tx::bytes [%0], [%1], %2, [%3];"
        :: "r"(dst), "l"(src), "r"(bytes), "r"(mbar) : "memory");
}

__device__ __forceinline__ void ldsm_x4(uint32_t* r, uint32_t addr) {
    asm volatile("ldmatrix.sync.aligned.m8n8.x4.shared.b16 {%0,%1,%2,%3}, [%4];"
        : "=r"(r[0]), "=r"(r[1]), "=r"(r[2]), "=r"(r[3]) : "r"(addr));
}

__device__ __forceinline__ void mma_bf16(float* d, const uint32_t* a, uint32_t b0, uint32_t b1) {
    asm volatile(
        "mma.sync.aligned.m16n8k16.row.col.f32.bf16.bf16.f32 "
        "{%0,%1,%2,%3}, {%4,%5,%6,%7}, {%8,%9}, {%0,%1,%2,%3};"
        : "+f"(d[0]), "+f"(d[1]), "+f"(d[2]), "+f"(d[3])
        : "r"(a[0]), "r"(a[1]), "r"(a[2]), "r"(a[3]), "r"(b0), "r"(b1));
}

// ---------------------------------------------------------------------------
// fp32 -> (bf16 hi, bf16 lo) conversion into chunked pre-swizzled layout.
// ---------------------------------------------------------------------------
__global__ void __launch_bounds__(256) convert_kernel(
    const float* __restrict__ in, __nv_bfloat16* __restrict__ hi,
    __nv_bfloat16* __restrict__ lo, int K, int RBtot, int rb_off)
{
    const int t = blockIdx.x * 256 + threadIdx.x;
    const int kq = K >> 2;
    const int r = t / kq;
    const int k = (t - r * kq) << 2;

    float4 v = *(const float4*)(in + (size_t)r * K + k);
    __nv_bfloat16 h0 = __float2bfloat16(v.x);
    __nv_bfloat16 h1 = __float2bfloat16(v.y);
    __nv_bfloat16 h2 = __float2bfloat16(v.z);
    __nv_bfloat16 h3 = __float2bfloat16(v.w);
    __nv_bfloat16 l0 = __float2bfloat16(v.x - __bfloat162float(h0));
    __nv_bfloat16 l1 = __float2bfloat16(v.y - __bfloat162float(h1));
    __nv_bfloat16 l2 = __float2bfloat16(v.z - __bfloat162float(h2));
    __nv_bfloat16 l3 = __float2bfloat16(v.w - __bfloat162float(h3));

    const int kc = k >> 6;
    const int rb = (r >> 7) + rb_off;
    const int rr = r & 127;
    const int c  = k & 63;
    size_t blkbytes = ((size_t)kc * RBtot + rb) * 16384;
    uint32_t off = (uint32_t)(rr * 128 + c * 2);
    off ^= (off >> 3) & 0x70;

    __nv_bfloat162 hp01 = __halves2bfloat162(h0, h1);
    __nv_bfloat162 hp23 = __halves2bfloat162(h2, h3);
    __nv_bfloat162 lp01 = __halves2bfloat162(l0, l1);
    __nv_bfloat162 lp23 = __halves2bfloat162(l2, l3);
    uint2 hu, lu;
    hu.x = *reinterpret_cast<uint32_t*>(&hp01); hu.y = *reinterpret_cast<uint32_t*>(&hp23);
    lu.x = *reinterpret_cast<uint32_t*>(&lp01); lu.y = *reinterpret_cast<uint32_t*>(&lp23);
    *reinterpret_cast<uint2*>((char*)hi + blkbytes + off) = hu;
    *reinterpret_cast<uint2*>((char*)lo + blkbytes + off) = lu;
}

__global__ void concat_bias_kernel(const float* __restrict__ bq, const float* __restrict__ bk,
                                   const float* __restrict__ bv)
{
    int t = blockIdx.x * 256 + threadIdx.x;
    if (t < 3 * DMODEL)
        g_bqkv[t] = (t < DMODEL) ? bq[t] : (t < 2 * DMODEL) ? bk[t - DMODEL] : bv[t - 2 * DMODEL];
}

// ---------------------------------------------------------------------------
// HMMA GEMM: C[M,N] = A[M,K'] @ W[N,K']^T (bf16x3 hi/lo split, fp32 accum).
// BM=BN=128, chunk K=64, 256 threads (8 warps, 2x4), warp tile 64x32.
// MODE 0: QKV scatter  MODE 1: +bias+residual  MODE 2: +bias+GELU
// ---------------------------------------------------------------------------
#define GEMM_STAGES 3
#define GEMM_SMEM_BYTES (1024 + GEMM_STAGES * 32768)

template <int MODE>
__global__ void __launch_bounds__(256, 2) tc_gemm(
    const __nv_bfloat16* __restrict__ Ahi, const __nv_bfloat16* __restrict__ Alo,
    const __nv_bfloat16* __restrict__ Whi, const __nv_bfloat16* __restrict__ Wlo,
    int KC, int MBtot, int NBtot,
    const float* __restrict__ bias, const float* __restrict__ add,
    float* __restrict__ C, int Ncols)
{
    extern __shared__ __align__(1024) char smem[];
    const uint32_t sb = smem_u32(smem);
    const uint32_t FULLB = sb;
    const uint32_t DATA = sb + 1024;

    const int tid = threadIdx.x;
    const int wid = tid >> 5;
    const int lane = tid & 31;
    const int mb = blockIdx.y;
    const int nb = blockIdx.x;
    const int m0 = mb * 128;
    const int n0 = nb * 128;
    const int wm = (wid >> 2) * 64;   // warp M offset (0/64)
    const int wn = (wid & 3) * 32;    // warp N offset (0/32/64/96)

    if (tid == 0)
        for (int s = 0; s < GEMM_STAGES; s++) MBARRIER_INIT(FULLB + 8 * s, 1);
    __syncthreads();

    const int NK = 3 * KC;

    auto issue = [&](int j, int s) {
        const int ph = j / KC;             // 0: hi*hi, 1: lo*hi, 2: hi*lo
        const int k = j - ph * KC;
        const __nv_bfloat16* Asrc = (ph == 1) ? Alo : Ahi;
        const __nv_bfloat16* Wsrc = (ph == 2) ? Wlo : Whi;
        const char* agm = (const char*)Asrc + ((size_t)k * MBtot + mb) * 16384;
        const char* bgm = (const char*)Wsrc + ((size_t)k * NBtot + nb) * 16384;
        const uint32_t full = FULLB + 8 * s;
        MBARRIER_EXPECT_TX(full, 32768);
        bulk_g2s(DATA + s * 32768, agm, 16384, full);
        bulk_g2s(DATA + s * 32768 + 16384, bgm, 16384, full);
    };

    if (tid == 0) {
        int pre = NK < GEMM_STAGES ? NK : GEMM_STAGES;
        for (int s = 0; s < pre; s++) issue(s, s);
    }

    float d[4][4][4];
#pragma unroll
    for (int mi = 0; mi < 4; mi++)
#pragma unroll
        for (int nj = 0; nj < 4; nj++)
#pragma unroll
            for (int r = 0; r < 4; r++) d[mi][nj][r] = 0.0f;

    // precompute thread-local row pieces
    const int rsel = lane & 15;         // row within 16-row group
    const int ksel = (lane >> 4) << 3;  // 0 or 8 (k sub-offset)

    int st = 0, phw = 0;
    for (int i = 0; i < NK; i++) {
        MBARRIER_WAIT_PARITY(FULLB + 8 * st, phw);
        const uint32_t Ab = DATA + st * 32768;
        const uint32_t Bb = Ab + 16384;

#pragma unroll
        for (int ks = 0; ks < 4; ks++) {
            const uint32_t kc2 = (uint32_t)((ks * 16 + ksel) * 2);
            uint32_t a[4][4];
#pragma unroll
            for (int mi = 0; mi < 4; mi++) {
                const int row = wm + mi * 16 + rsel;
                ldsm_x4(a[mi], Ab + row * 128 + (kc2 ^ ((row & 7) << 4)));
            }
            uint32_t bfr[4][2];
#pragma unroll
            for (int g = 0; g < 2; g++) {
                const int row = wn + g * 16 + rsel;
                uint32_t r4[4];
                ldsm_x4(r4, Bb + row * 128 + (kc2 ^ ((row & 7) << 4)));
                bfr[g * 2 + 0][0] = r4[0]; bfr[g * 2 + 0][1] = r4[2];
                bfr[g * 2 + 1][0] = r4[1]; bfr[g * 2 + 1][1] = r4[3];
            }
#pragma unroll
            for (int mi = 0; mi < 4; mi++)
#pragma unroll
                for (int nj = 0; nj < 4; nj++)
                    mma_bf16(d[mi][nj], a[mi], bfr[nj][0], bfr[nj][1]);
        }

        __syncthreads();
        if (tid == 0 && i + GEMM_STAGES < NK) issue(i + GEMM_STAGES, st);
        if (++st == GEMM_STAGES) { st = 0; phw ^= 1; }
    }

    // ------------------- epilogue -------------------
    const int gr = lane >> 2;           // group row 0..7
    const int gc = (lane & 3) << 1;     // col pair base
#pragma unroll
    for (int mi = 0; mi < 4; mi++) {
#pragma unroll
        for (int nj = 0; nj < 4; nj++) {
            const int col = n0 + wn + nj * 8 + gc;
            const float bx = bias[col], by = bias[col + 1];
#pragma unroll
            for (int half = 0; half < 2; half++) {
                const int m = m0 + wm + mi * 16 + gr + half * 8;
                float ox = d[mi][nj][half * 2 + 0] + bx;
                float oy = d[mi][nj][half * 2 + 1] + by;
                if (MODE == 0) {
                    const int which = col >> 10;
                    float* outp = (which == 0) ? g_Q : (which == 1) ? g_K : g_V;
                    const int np = col & 1023;
                    const int b = m >> 11;
                    const int s = m & (SEQ - 1);
                    const int hh = np >> 6;
                    const int dk = np & 63;
                    float2 o; o.x = ox; o.y = oy;
                    *(float2*)&outp[(((size_t)(b * NHEAD + hh)) * SEQ + s) * DHEAD + dk] = o;
                } else if (MODE == 1) {
                    float2 a2 = *(const float2*)(add + (size_t)m * Ncols + col);
                    float2 o; o.x = ox + a2.x; o.y = oy + a2.y;
                    *(float2*)(C + (size_t)m * Ncols + col) = o;
                } else {
                    float2 o;
                    o.x = 0.5f * ox * (1.0f + erff(ox * 0.70710678118654752f));
                    o.y = 0.5f * oy * (1.0f + erff(oy * 0.70710678118654752f));
                    *(float2*)(C + (size_t)m * Ncols + col) = o;
                }
            }
        }
    }
}

// ---------------------------------------------------------------------------
// Flash attention (fp32), unchanged.
// ---------------------------------------------------------------------------
__global__ void __launch_bounds__(256) attn_kernel(
    const float* __restrict__ Qg, const float* __restrict__ Kg,
    const float* __restrict__ Vg, float* __restrict__ ctx)
{
    __shared__ float Qs[64 * 64];
    __shared__ float KPs[64 * 64];
    __shared__ float Vs[64 * 64];

    const int tid = threadIdx.x;
    const int qt = blockIdx.x;
    const int hh = blockIdx.y;
    const int bb = blockIdx.z;
    const int tx = tid & 15;
    const int ty = tid >> 4;

    const size_t headbase = (size_t)(bb * NHEAD + hh) * SEQ * DHEAD;
    const float* Qhead = Qg + headbase + (size_t)qt * 64 * DHEAD;
    const float* Khead = Kg + headbase;
    const float* Vhead = Vg + headbase;

    const float scale = 0.125f;
#pragma unroll
    for (int i = 0; i < 4; i++) {
        int idx = tid + i * 256;
        float4 q = ((const float4*)Qhead)[idx];
        q.x *= scale; q.y *= scale; q.z *= scale; q.w *= scale;
        ((float4*)Qs)[idx] = q;
    }

    float acc[4][4];
    float mi[4], li[4];
#pragma unroll
    for (int i = 0; i < 4; i++) {
        mi[i] = -1e30f; li[i] = 0.0f;
#pragma unroll
        for (int j = 0; j < 4; j++) acc[i][j] = 0.0f;
    }

    for (int kt = 0; kt <= qt; kt++) {
        __syncthreads();
#pragma unroll
        for (int i = 0; i < 4; i++) {
            int idx = tid + i * 256;
            ((float4*)KPs)[idx] = ((const float4*)(Khead + (size_t)kt * 64 * DHEAD))[idx];
            ((float4*)Vs)[idx]  = ((const float4*)(Vhead + (size_t)kt * 64 * DHEAD))[idx];
        }
        __syncthreads();

        float s[4][4];
#pragma unroll
        for (int i = 0; i < 4; i++)
#pragma unroll
            for (int j = 0; j < 4; j++) s[i][j] = 0.0f;

#pragma unroll 4
        for (int d4 = 0; d4 < 16; d4++) {
            float4 q4[4], k4[4];
#pragma unroll
            for (int i = 0; i < 4; i++) q4[i] = ((const float4*)Qs)[(ty * 4 + i) * 16 + d4];
#pragma unroll
            for (int j = 0; j < 4; j++) k4[j] = ((const float4*)KPs)[(tx * 4 + j) * 16 + d4];
#pragma unroll
            for (int i = 0; i < 4; i++)
#pragma unroll
                for (int j = 0; j < 4; j++) {
                    s[i][j] = fmaf(q4[i].x, k4[j].x, s[i][j]);
                    s[i][j] = fmaf(q4[i].y, k4[j].y, s[i][j]);
                    s[i][j] = fmaf(q4[i].z, k4[j].z, s[i][j]);
                    s[i][j] = fmaf(q4[i].w, k4[j].w, s[i][j]);
                }
        }

        if (kt == qt) {
#pragma unroll
            for (int i = 0; i < 4; i++)
#pragma unroll
                for (int j = 0; j < 4; j++)
                    if (tx * 4 + j > ty * 4 + i) s[i][j] = -1e30f;
        }

        __syncthreads();

#pragma unroll
        for (int i = 0; i < 4; i++) {
            float lm = fmaxf(fmaxf(s[i][0], s[i][1]), fmaxf(s[i][2], s[i][3]));
#pragma unroll
            for (int off = 1; off < 16; off <<= 1)
                lm = fmaxf(lm, __shfl_xor_sync(0xffffffffu, lm, off));
            float mnew = fmaxf(mi[i], lm);
            float corr = __expf(mi[i] - mnew);
            mi[i] = mnew;
            float rs = 0.0f;
#pragma unroll
            for (int j = 0; j < 4; j++) {
                float p = __expf(s[i][j] - mnew);
                KPs[(ty * 4 + i) * 64 + tx * 4 + j] = p;
                rs += p;
            }
#pragma unroll
            for (int off = 1; off < 16; off <<= 1)
                rs += __shfl_xor_sync(0xffffffffu, rs, off);
            li[i] = li[i] * corr + rs;
#pragma unroll
            for (int dc = 0; dc < 4; dc++) acc[i][dc] *= corr;
        }
        __syncthreads();

#pragma unroll 4
        for (int k4 = 0; k4 < 16; k4++) {
            float4 p4[4];
#pragma unroll
            for (int i = 0; i < 4; i++) p4[i] = ((const float4*)KPs)[(ty * 4 + i) * 16 + k4];
#pragma unroll
            for (int kk = 0; kk < 4; kk++) {
                float4 v4 = ((const float4*)Vs)[(k4 * 4 + kk) * 16 + tx];
#pragma unroll
                for (int i = 0; i < 4; i++) {
                    float p = (kk == 0) ? p4[i].x : (kk == 1) ? p4[i].y : (kk == 2) ? p4[i].z : p4[i].w;
                    acc[i][0] = fmaf(p, v4.x, acc[i][0]);
                    acc[i][1] = fmaf(p, v4.y, acc[i][1]);
                    acc[i][2] = fmaf(p, v4.z, acc[i][2]);
                    acc[i][3] = fmaf(p, v4.w, acc[i][3]);
                }
            }
        }
    }

#pragma unroll
    for (int i = 0; i < 4; i++) {
        const float inv = 1.0f / li[i];
        const int qg = qt * 64 + ty * 4 + i;
        float4 o;
        o.x = acc[i][0] * inv; o.y = acc[i][1] * inv;
        o.z = acc[i][2] * inv; o.w = acc[i][3] * inv;
        *(float4*)&ctx[((size_t)bb * SEQ + qg) * DMODEL + hh * DHEAD + tx * 4] = o;
    }
}

// ---------------------------------------------------------------------------
// LayerNorm (unchanged).
// ---------------------------------------------------------------------------
__global__ void __launch_bounds__(256) ln_kernel(
    const float* __restrict__ in, const float* __restrict__ sc,
    const float* __restrict__ bi, float* __restrict__ out)
{
    __shared__ float red0[8], red1[8];
    __shared__ float s_mu, s_inv;
    const int row = blockIdx.x;
    const int tid = threadIdx.x;

    float4 x = ((const float4*)(in + (size_t)row * DMODEL))[tid];
    float sum = x.x + x.y + x.z + x.w;
    float sq  = x.x * x.x + x.y * x.y + x.z * x.z + x.w * x.w;
#pragma unroll
    for (int o = 16; o; o >>= 1) {
        sum += __shfl_xor_sync(0xffffffffu, sum, o);
        sq  += __shfl_xor_sync(0xffffffffu, sq, o);
    }
    if ((tid & 31) == 0) { red0[tid >> 5] = sum; red1[tid >> 5] = sq; }
    __syncthreads();
    if (tid < 32) {
        float s = (tid < 8) ? red0[tid] : 0.0f;
        float q = (tid < 8) ? red1[tid] : 0.0f;
#pragma unroll
        for (int o = 4; o; o >>= 1) {
            s += __shfl_xor_sync(0xffffffffu, s, o);
            q += __shfl_xor_sync(0xffffffffu, q, o);
        }
        if (tid == 0) {
            float mu = s * (1.0f / DMODEL);
            float var = q * (1.0f / DMODEL) - mu * mu;
            s_mu = mu;
            s_inv = rsqrtf(var + 1e-5f);
        }
    }
    __syncthreads();
    const float mu = s_mu, inv = s_inv;
    float4 g = ((const float4*)sc)[tid];
    float4 b = ((const float4*)bi)[tid];
    float4 o;
    o.x = (x.x - mu) * inv * g.x + b.x;
    o.y = (x.y - mu) * inv * g.y + b.y;
    o.z = (x.z - mu) * inv * g.z + b.z;
    o.w = (x.w - mu) * inv * g.w + b.w;
    ((float4*)(out + (size_t)row * DMODEL))[tid] = o;
}

// ---------------------------------------------------------------------------
extern "C" void kernel_launch(void* const* d_in, const int* in_sizes, int n_in,
                              void* d_out, int out_size)
{
    (void)in_sizes; (void)n_in; (void)out_size;
    const float* x    = (const float*)d_in[0];
    const float* wq   = (const float*)d_in[2];
    const float* bq   = (const float*)d_in[3];
    const float* wk   = (const float*)d_in[4];
    const float* bk   = (const float*)d_in[5];
    const float* wv   = (const float*)d_in[6];
    const float* bv   = (const float*)d_in[7];
    const float* wo   = (const float*)d_in[8];
    const float* bo   = (const float*)d_in[9];
    const float* w1   = (const float*)d_in[10];
    const float* b1   = (const float*)d_in[11];
    const float* w2   = (const float*)d_in[12];
    const float* b2   = (const float*)d_in[13];
    const float* ln1s = (const float*)d_in[14];
    const float* ln1b = (const float*)d_in[15];
    const float* ln2s = (const float*)d_in[16];
    const float* ln2b = (const float*)d_in[17];
    float* out = (float*)d_out;

    float *Q, *K, *V, *ctx, *res1, *h, *ff, *res2, *bqkv;
    cudaGetSymbolAddress((void**)&Q,    g_Q);
    cudaGetSymbolAddress((void**)&K,    g_K);
    cudaGetSymbolAddress((void**)&V,    g_V);
    cudaGetSymbolAddress((void**)&ctx,  g_ctx);
    cudaGetSymbolAddress((void**)&res1, g_res1);
    cudaGetSymbolAddress((void**)&h,    g_h);
    cudaGetSymbolAddress((void**)&ff,   g_ff);
    cudaGetSymbolAddress((void**)&res2, g_res2);
    cudaGetSymbolAddress((void**)&bqkv, g_bqkv);

    __nv_bfloat16 *x2h, *x2l, *c2h, *c2l, *h2h, *h2l, *f2h, *f2l;
    __nv_bfloat16 *wqkvh, *wqkvl, *woh, *wol, *w1h, *w1l, *w2h, *w2l;
    cudaGetSymbolAddress((void**)&x2h, g_x2hi);   cudaGetSymbolAddress((void**)&x2l, g_x2lo);
    cudaGetSymbolAddress((void**)&c2h, g_ctx2hi); cudaGetSymbolAddress((void**)&c2l, g_ctx2lo);
    cudaGetSymbolAddress((void**)&h2h, g_h2hi);   cudaGetSymbolAddress((void**)&h2l, g_h2lo);
    cudaGetSymbolAddress((void**)&f2h, g_ff2hi);  cudaGetSymbolAddress((void**)&f2l, g_ff2lo);
    cudaGetSymbolAddress((void**)&wqkvh, g_wqkvhi); cudaGetSymbolAddress((void**)&wqkvl, g_wqkvlo);
    cudaGetSymbolAddress((void**)&woh, g_wohi);   cudaGetSymbolAddress((void**)&wol, g_wolo);
    cudaGetSymbolAddress((void**)&w1h, g_w1hi);   cudaGetSymbolAddress((void**)&w1l, g_w1lo);
    cudaGetSymbolAddress((void**)&w2h, g_w2hi);   cudaGetSymbolAddress((void**)&w2l, g_w2lo);

    cudaFuncSetAttribute(tc_gemm<0>, cudaFuncAttributeMaxDynamicSharedMemorySize, GEMM_SMEM_BYTES);
    cudaFuncSetAttribute(tc_gemm<1>, cudaFuncAttributeMaxDynamicSharedMemorySize, GEMM_SMEM_BYTES);
    cudaFuncSetAttribute(tc_gemm<2>, cudaFuncAttributeMaxDynamicSharedMemorySize, GEMM_SMEM_BYTES);

    const dim3 blk256(256);

    // --- weight + input conversions ---
    convert_kernel<<<MROWS * DMODEL / 1024, blk256>>>(x,  x2h, x2l, DMODEL, MBTOT, 0);
    convert_kernel<<<DMODEL * DMODEL / 1024, blk256>>>(wq, wqkvh, wqkvl, DMODEL, 24, 0);
    convert_kernel<<<DMODEL * DMODEL / 1024, blk256>>>(wk, wqkvh, wqkvl, DMODEL, 24, 8);
    convert_kernel<<<DMODEL * DMODEL / 1024, blk256>>>(wv, wqkvh, wqkvl, DMODEL, 24, 16);
    convert_kernel<<<DMODEL * DMODEL / 1024, blk256>>>(wo, woh, wol, DMODEL, 8, 0);
    convert_kernel<<<DFF * DMODEL / 1024, blk256>>>(w1, w1h, w1l, DMODEL, 32, 0);
    convert_kernel<<<DMODEL * DFF / 1024, blk256>>>(w2, w2h, w2l, DFF, 8, 0);
    concat_bias_kernel<<<12, blk256>>>(bq, bk, bv);

    // --- QKV: one fused GEMM (N=3072) with head-split scatter epilogue ---
    tc_gemm<0><<<dim3(24, MBTOT), blk256, GEMM_SMEM_BYTES>>>(
        x2h, x2l, wqkvh, wqkvl, DMODEL / 64, MBTOT, 24, bqkv, nullptr, nullptr, 3072);

    // --- attention ---
    attn_kernel<<<dim3(SEQ / 64, NHEAD, BATCH), blk256>>>(Q, K, V, ctx);

    // --- O projection + residual(x) ---
    convert_kernel<<<MROWS * DMODEL / 1024, blk256>>>(ctx, c2h, c2l, DMODEL, MBTOT, 0);
    tc_gemm<1><<<dim3(8, MBTOT), blk256, GEMM_SMEM_BYTES>>>(
        c2h, c2l, woh, wol, DMODEL / 64, MBTOT, 8, bo, x, res1, DMODEL);
    ln_kernel<<<MROWS, blk256>>>(res1, ln1s, ln1b, h);

    // --- FFN1 + GELU ---
    convert_kernel<<<MROWS * DMODEL / 1024, blk256>>>(h, h2h, h2l, DMODEL, MBTOT, 0);
    tc_gemm<2><<<dim3(32, MBTOT), blk256, GEMM_SMEM_BYTES>>>(
        h2h, h2l, w1h, w1l, DMODEL / 64, MBTOT, 32, b1, nullptr, ff, DFF);

    // --- FFN2 + residual(h) ---
    convert_kernel<<<(size_t)MROWS * DFF / 1024, blk256>>>(ff, f2h, f2l, DFF, MBTOT, 0);
    tc_gemm<1><<<dim3(8, MBTOT), blk256, GEMM_SMEM_BYTES>>>(
        f2h, f2l, w2h, w2l, DFF / 64, MBTOT, 8, b2, h, res2, DMODEL);
    ln_kernel<<<MROWS, blk256>>>(res2, ln2s, ln2b, out);
}

// round 4
// speedup vs baseline: 3.9801x; 2.2083x over previous
#include <cuda_runtime.h>
#include <cuda_bf16.h>
#include <math.h>
#include <stdint.h>

// ---------------------------------------------------------------------------
// GPT block: B=4, S=2048, D_MODEL=1024, H=16, DK=64, DFF=4096, fp32, causal.
// Round-4: HMMA everywhere. bf16x3 GEMMs + bf16x3 flash-attention (FA2-style),
// all activation hi/lo conversions fused into producer epilogues.
// ---------------------------------------------------------------------------

#define BATCH  4
#define SEQ    2048
#define DMODEL 1024
#define NHEAD  16
#define DHEAD  64
#define DFF    4096
#define MROWS  (BATCH * SEQ)   // 8192
#define MBTOT  (MROWS / 128)   // 64

// ---------------- fp32 scratch ----------------
__device__ float g_res1[MROWS * DMODEL];
__device__ float g_h[MROWS * DMODEL];
__device__ float g_res2[MROWS * DMODEL];
__device__ float g_bqkv[3 * DMODEL];

// ---------------- bf16 hi/lo scratch ----------------
// GEMM-A chunk layout: [kc][rb] blocks of 128rows x 64cols bf16 = 16KB, SW128.
__device__ __align__(1024) __nv_bfloat16 g_x2hi[MROWS * DMODEL];
__device__ __align__(1024) __nv_bfloat16 g_x2lo[MROWS * DMODEL];
__device__ __align__(1024) __nv_bfloat16 g_ctx2hi[MROWS * DMODEL];
__device__ __align__(1024) __nv_bfloat16 g_ctx2lo[MROWS * DMODEL];
__device__ __align__(1024) __nv_bfloat16 g_h2hi[MROWS * DMODEL];
__device__ __align__(1024) __nv_bfloat16 g_h2lo[MROWS * DMODEL];
__device__ __align__(1024) __nv_bfloat16 g_ff2hi[(size_t)MROWS * DFF];
__device__ __align__(1024) __nv_bfloat16 g_ff2lo[(size_t)MROWS * DFF];
// QKV per-head tile layout: [b*H+h][t=s/64] tiles of 64rows x 64cols bf16 = 8KB, SW128.
__device__ __align__(1024) __nv_bfloat16 g_Qh[MROWS * DMODEL];
__device__ __align__(1024) __nv_bfloat16 g_Ql[MROWS * DMODEL];
__device__ __align__(1024) __nv_bfloat16 g_Kh[MROWS * DMODEL];
__device__ __align__(1024) __nv_bfloat16 g_Kl[MROWS * DMODEL];
__device__ __align__(1024) __nv_bfloat16 g_Vh[MROWS * DMODEL];
__device__ __align__(1024) __nv_bfloat16 g_Vl[MROWS * DMODEL];
// weights
__device__ __align__(1024) __nv_bfloat16 g_wqkvhi[3 * DMODEL * DMODEL];
__device__ __align__(1024) __nv_bfloat16 g_wqkvlo[3 * DMODEL * DMODEL];
__device__ __align__(1024) __nv_bfloat16 g_wohi[DMODEL * DMODEL];
__device__ __align__(1024) __nv_bfloat16 g_wolo[DMODEL * DMODEL];
__device__ __align__(1024) __nv_bfloat16 g_w1hi[DFF * DMODEL];
__device__ __align__(1024) __nv_bfloat16 g_w1lo[DFF * DMODEL];
__device__ __align__(1024) __nv_bfloat16 g_w2hi[DMODEL * DFF];
__device__ __align__(1024) __nv_bfloat16 g_w2lo[DMODEL * DFF];

// ---------------------------------------------------------------------------
// PTX helpers (base-target only)
// ---------------------------------------------------------------------------
__device__ __forceinline__ uint32_t smem_u32(const void* p) {
    uint32_t a;
    asm("{ .reg .u64 t; cvta.to.shared.u64 t, %1; cvt.u32.u64 %0, t; }" : "=r"(a) : "l"(p));
    return a;
}

#define MBARRIER_INIT(addr, cnt) \
    asm volatile("mbarrier.init.shared.b64 [%0], %1;" :: "r"((uint32_t)(addr)), "r"((uint32_t)(cnt)) : "memory")

#define MBARRIER_EXPECT_TX(addr, bytes) \
    asm volatile("mbarrier.arrive.expect_tx.shared.b64 _, [%0], %1;" :: "r"((uint32_t)(addr)), "r"((uint32_t)(bytes)) : "memory")

#define MBARRIER_WAIT_PARITY(mbar_smem_addr, phase_parity) do { \
    uint32_t _mbar = (uint32_t)(mbar_smem_addr); \
    uint32_t _parity = (uint32_t)(phase_parity); \
    uint32_t _done; \
    asm volatile( \
        "{\n\t.reg .pred p;\n\t" \
        "mbarrier.try_wait.parity.acquire.cta.shared::cta.b64 p, [%1], %2;\n\t" \
        "selp.b32 %0, 1, 0, p;\n\t}" \
        : "=r"(_done) : "r"(_mbar), "r"(_parity) : "memory"); \
    if (!_done) { \
        asm volatile( \
            "{\n\t.reg .pred P1;\n\t" \
            "WAIT_LOOP_%=:\n\t" \
            "mbarrier.try_wait.parity.acquire.cta.shared::cta.b64 P1, [%0], %1, 0x989680;\n\t" \
            "@P1 bra.uni WAIT_DONE_%=;\n\t" \
            "bra.uni WAIT_LOOP_%=;\n\t" \
            "WAIT_DONE_%=:\n\t}" \
            :: "r"(_mbar), "r"(_parity) : "memory"); \
    } \
} while(0)

__device__ __forceinline__ void bulk_g2s(uint32_t dst, const void* src, uint32_t bytes, uint32_t mbar) {
    asm volatile(
        "cp.async.bulk.shared::cluster.global.mbarrier::complete_tx::bytes [%0], [%1], %2, [%3];"
        :: "r"(dst), "l"(src), "r"(bytes), "r"(mbar) : "memory");
}

__device__ __forceinline__ void ldsm_x4(uint32_t* r, uint32_t addr) {
    asm volatile("ldmatrix.sync.aligned.m8n8.x4.shared.b16 {%0,%1,%2,%3}, [%4];"
        : "=r"(r[0]), "=r"(r[1]), "=r"(r[2]), "=r"(r[3]) : "r"(addr));
}

__device__ __forceinline__ void ldsm_x4_t(uint32_t* r, uint32_t addr) {
    asm volatile("ldmatrix.sync.aligned.m8n8.x4.trans.shared.b16 {%0,%1,%2,%3}, [%4];"
        : "=r"(r[0]), "=r"(r[1]), "=r"(r[2]), "=r"(r[3]) : "r"(addr));
}

__device__ __forceinline__ void mma_bf16(float* d, const uint32_t* a, uint32_t b0, uint32_t b1) {
    asm volatile(
        "mma.sync.aligned.m16n8k16.row.col.f32.bf16.bf16.f32 "
        "{%0,%1,%2,%3}, {%4,%5,%6,%7}, {%8,%9}, {%0,%1,%2,%3};"
        : "+f"(d[0]), "+f"(d[1]), "+f"(d[2]), "+f"(d[3])
        : "r"(a[0]), "r"(a[1]), "r"(a[2]), "r"(a[3]), "r"(b0), "r"(b1));
}

__device__ __forceinline__ uint32_t pack_bf16(float x, float y) {
    __nv_bfloat162 p = __halves2bfloat162(__float2bfloat16(x), __float2bfloat16(y));
    return *reinterpret_cast<uint32_t*>(&p);
}
// split: returns hi pair, residuals in rx, ry
__device__ __forceinline__ uint32_t split_hi(float x, float y, float& rx, float& ry) {
    __nv_bfloat16 hx = __float2bfloat16(x);
    __nv_bfloat16 hy = __float2bfloat16(y);
    rx = x - __bfloat162float(hx);
    ry = y - __bfloat162float(hy);
    __nv_bfloat162 p = __halves2bfloat162(hx, hy);
    return *reinterpret_cast<uint32_t*>(&p);
}

// ---------------------------------------------------------------------------
// fp32 -> bf16 hi/lo conversion into GEMM-A chunk layout (x + weights only).
// ---------------------------------------------------------------------------
__global__ void __launch_bounds__(256) convert_kernel(
    const float* __restrict__ in, __nv_bfloat16* __restrict__ hi,
    __nv_bfloat16* __restrict__ lo, int K, int RBtot, int rb_off)
{
    const int t = blockIdx.x * 256 + threadIdx.x;
    const int kq = K >> 2;
    const int r = t / kq;
    const int k = (t - r * kq) << 2;

    float4 v = *(const float4*)(in + (size_t)r * K + k);
    float l0, l1, l2, l3;
    uint32_t h01 = split_hi(v.x, v.y, l0, l1);
    uint32_t h23 = split_hi(v.z, v.w, l2, l3);
    uint32_t p01 = pack_bf16(l0, l1);
    uint32_t p23 = pack_bf16(l2, l3);

    const int kc = k >> 6;
    const int rb = (r >> 7) + rb_off;
    const int rr = r & 127;
    const int c  = k & 63;
    size_t blkbytes = ((size_t)kc * RBtot + rb) * 16384;
    uint32_t off = (uint32_t)(rr * 128 + c * 2);
    off ^= (off >> 3) & 0x70;

    uint2 hu, lu;
    hu.x = h01; hu.y = h23;
    lu.x = p01; lu.y = p23;
    *reinterpret_cast<uint2*>((char*)hi + blkbytes + off) = hu;
    *reinterpret_cast<uint2*>((char*)lo + blkbytes + off) = lu;
}

__global__ void concat_bias_kernel(const float* __restrict__ bq, const float* __restrict__ bk,
                                   const float* __restrict__ bv)
{
    int t = blockIdx.x * 256 + threadIdx.x;
    if (t < 3 * DMODEL)
        g_bqkv[t] = (t < DMODEL) ? bq[t] : (t < 2 * DMODEL) ? bk[t - DMODEL] : bv[t - 2 * DMODEL];
}

// ---------------------------------------------------------------------------
// HMMA GEMM: C[M,N] = A[M,K'] @ W[N,K']^T (bf16x3 hi/lo split, fp32 accum).
// BM=BN=128, chunk K=64, 256 threads (8 warps), warp tile 64x32.
// MODE 0: QKV -> bf16 hi/lo per-head tiles (Q pre-scaled by 1/8)
// MODE 1: +bias +residual -> fp32 row-major
// MODE 2: +bias +GELU -> bf16 hi/lo chunk layout (g_ff2hi/g_ff2lo)
// ---------------------------------------------------------------------------
#define GEMM_STAGES 3
#define GEMM_SMEM_BYTES (1024 + GEMM_STAGES * 32768)

template <int MODE>
__global__ void __launch_bounds__(256, 2) tc_gemm(
    const __nv_bfloat16* __restrict__ Ahi, const __nv_bfloat16* __restrict__ Alo,
    const __nv_bfloat16* __restrict__ Whi, const __nv_bfloat16* __restrict__ Wlo,
    int KC, int MBtot, int NBtot,
    const float* __restrict__ bias, const float* __restrict__ add,
    float* __restrict__ C, int Ncols)
{
    extern __shared__ __align__(1024) char smem[];
    const uint32_t sb = smem_u32(smem);
    const uint32_t FULLB = sb;
    const uint32_t DATA = sb + 1024;

    const int tid = threadIdx.x;
    const int wid = tid >> 5;
    const int lane = tid & 31;
    const int mb = blockIdx.y;
    const int nb = blockIdx.x;
    const int m0 = mb * 128;
    const int n0 = nb * 128;
    const int wm = (wid >> 2) * 64;
    const int wn = (wid & 3) * 32;

    if (tid == 0)
        for (int s = 0; s < GEMM_STAGES; s++) MBARRIER_INIT(FULLB + 8 * s, 1);
    __syncthreads();

    const int NK = 3 * KC;

    auto issue = [&](int j, int s) {
        const int ph = j / KC;
        const int k = j - ph * KC;
        const __nv_bfloat16* Asrc = (ph == 1) ? Alo : Ahi;
        const __nv_bfloat16* Wsrc = (ph == 2) ? Wlo : Whi;
        const char* agm = (const char*)Asrc + ((size_t)k * MBtot + mb) * 16384;
        const char* bgm = (const char*)Wsrc + ((size_t)k * NBtot + nb) * 16384;
        const uint32_t full = FULLB + 8 * s;
        MBARRIER_EXPECT_TX(full, 32768);
        bulk_g2s(DATA + s * 32768, agm, 16384, full);
        bulk_g2s(DATA + s * 32768 + 16384, bgm, 16384, full);
    };

    if (tid == 0) {
        int pre = NK < GEMM_STAGES ? NK : GEMM_STAGES;
        for (int s = 0; s < pre; s++) issue(s, s);
    }

    float d[4][4][4];
#pragma unroll
    for (int mi = 0; mi < 4; mi++)
#pragma unroll
        for (int nj = 0; nj < 4; nj++)
#pragma unroll
            for (int r = 0; r < 4; r++) d[mi][nj][r] = 0.0f;

    const int rsel = lane & 15;
    const int ksel = (lane >> 4) << 3;

    int st = 0, phw = 0;
    for (int i = 0; i < NK; i++) {
        MBARRIER_WAIT_PARITY(FULLB + 8 * st, phw);
        const uint32_t Ab = DATA + st * 32768;
        const uint32_t Bb = Ab + 16384;

#pragma unroll
        for (int ks = 0; ks < 4; ks++) {
            const uint32_t kc2 = (uint32_t)((ks * 16 + ksel) * 2);
            uint32_t a[4][4];
#pragma unroll
            for (int mi = 0; mi < 4; mi++) {
                const int row = wm + mi * 16 + rsel;
                ldsm_x4(a[mi], Ab + row * 128 + (kc2 ^ ((row & 7) << 4)));
            }
            uint32_t bfr[4][2];
#pragma unroll
            for (int g = 0; g < 2; g++) {
                const int row = wn + g * 16 + rsel;
                uint32_t r4[4];
                ldsm_x4(r4, Bb + row * 128 + (kc2 ^ ((row & 7) << 4)));
                bfr[g * 2 + 0][0] = r4[0]; bfr[g * 2 + 0][1] = r4[2];
                bfr[g * 2 + 1][0] = r4[1]; bfr[g * 2 + 1][1] = r4[3];
            }
#pragma unroll
            for (int mi = 0; mi < 4; mi++)
#pragma unroll
                for (int nj = 0; nj < 4; nj++)
                    mma_bf16(d[mi][nj], a[mi], bfr[nj][0], bfr[nj][1]);
        }

        __syncthreads();
        if (tid == 0 && i + GEMM_STAGES < NK) issue(i + GEMM_STAGES, st);
        if (++st == GEMM_STAGES) { st = 0; phw ^= 1; }
    }

    // ------------------- epilogue -------------------
    const int gr = lane >> 2;
    const int gc = (lane & 3) << 1;
#pragma unroll
    for (int mi = 0; mi < 4; mi++) {
#pragma unroll
        for (int nj = 0; nj < 4; nj++) {
            const int col = n0 + wn + nj * 8 + gc;
            const float bx = bias[col], by = bias[col + 1];
#pragma unroll
            for (int half = 0; half < 2; half++) {
                const int m = m0 + wm + mi * 16 + gr + half * 8;
                float ox = d[mi][nj][half * 2 + 0] + bx;
                float oy = d[mi][nj][half * 2 + 1] + by;
                if (MODE == 0) {
                    const int which = col >> 10;
                    const int np = col & 1023;
                    const int hh = np >> 6;
                    const int dk = np & 63;
                    const int b = m >> 11;
                    const int s2 = m & (SEQ - 1);
                    if (which == 0) { ox *= 0.125f; oy *= 0.125f; }
                    float lx, ly;
                    uint32_t hp = split_hi(ox, oy, lx, ly);
                    uint32_t lp = pack_bf16(lx, ly);
                    size_t base = (((size_t)(b * NHEAD + hh)) * SEQ + (s2 & ~63)) * DHEAD;
                    uint32_t off = (uint32_t)((s2 & 63) * 128 + dk * 2);
                    off ^= (off >> 3) & 0x70;
                    __nv_bfloat16* dh = (which == 0) ? g_Qh : (which == 1) ? g_Kh : g_Vh;
                    __nv_bfloat16* dl = (which == 0) ? g_Ql : (which == 1) ? g_Kl : g_Vl;
                    *(uint32_t*)((char*)(dh + base) + off) = hp;
                    *(uint32_t*)((char*)(dl + base) + off) = lp;
                } else if (MODE == 1) {
                    float2 a2 = *(const float2*)(add + (size_t)m * Ncols + col);
                    float2 o; o.x = ox + a2.x; o.y = oy + a2.y;
                    *(float2*)(C + (size_t)m * Ncols + col) = o;
                } else {
                    float gx = 0.5f * ox * (1.0f + erff(ox * 0.70710678118654752f));
                    float gy = 0.5f * oy * (1.0f + erff(oy * 0.70710678118654752f));
                    float lx, ly;
                    uint32_t hp = split_hi(gx, gy, lx, ly);
                    uint32_t lp = pack_bf16(lx, ly);
                    const int kc = col >> 6;
                    const int c = col & 63;
                    const int rb = m >> 7;
                    const int rr = m & 127;
                    size_t blkbytes = ((size_t)(kc * MBTOT + rb)) * 16384;
                    uint32_t off = (uint32_t)(rr * 128 + c * 2);
                    off ^= (off >> 3) & 0x70;
                    *(uint32_t*)((char*)g_ff2hi + blkbytes + off) = hp;
                    *(uint32_t*)((char*)g_ff2lo + blkbytes + off) = lp;
                }
            }
        }
    }
}

// ---------------------------------------------------------------------------
// HMMA flash attention, bf16x3 splits. Block = 128 threads (4 warps), 64 q rows.
// Warp w owns q rows [w*16, w*16+16). kv tiles of 64 rows, 2-stage pipeline.
// Output: ctx written directly as bf16 hi/lo GEMM-A chunks (g_ctx2hi/lo).
// ---------------------------------------------------------------------------
#define ATT_STAGES 2
#define ATT_SMEM (1024 + 16384 + ATT_STAGES * 32768)

__global__ void __launch_bounds__(128, 2) attn_mma_kernel(
    const __nv_bfloat16* __restrict__ Qh, const __nv_bfloat16* __restrict__ Ql,
    const __nv_bfloat16* __restrict__ Kh, const __nv_bfloat16* __restrict__ Kl,
    const __nv_bfloat16* __restrict__ Vh, const __nv_bfloat16* __restrict__ Vl)
{
    extern __shared__ __align__(1024) char smem[];
    const uint32_t sb = smem_u32(smem);
    const uint32_t QBAR = sb;
    const uint32_t FULLB = sb + 8;
    const uint32_t SQ = sb + 1024;          // Qhi 8KB; Qlo at +8192
    const uint32_t SKV = SQ + 16384;        // per stage: Khi,Klo,Vhi,Vlo 8KB each

    const int tid = threadIdx.x;
    const int wid = tid >> 5;
    const int lane = tid & 31;
    const int qt = blockIdx.x;              // 0..31
    const int hh = blockIdx.y;
    const int bb = blockIdx.z;
    const int q0 = qt * 64;
    const int T = qt + 1;

    const size_t headoff = (size_t)(bb * NHEAD + hh) * SEQ * DHEAD;

    if (tid == 0) {
        MBARRIER_INIT(QBAR, 1);
        MBARRIER_INIT(FULLB, 1);
        MBARRIER_INIT(FULLB + 8, 1);
    }
    __syncthreads();

    if (tid == 0) {
        MBARRIER_EXPECT_TX(QBAR, 16384);
        bulk_g2s(SQ,        Qh + headoff + (size_t)qt * 4096, 8192, QBAR);
        bulk_g2s(SQ + 8192, Ql + headoff + (size_t)qt * 4096, 8192, QBAR);
        const int pre = T < ATT_STAGES ? T : ATT_STAGES;
        for (int s = 0; s < pre; s++) {
            const uint32_t full = FULLB + 8 * s;
            MBARRIER_EXPECT_TX(full, 32768);
            const size_t kv = headoff + (size_t)s * 4096;
            bulk_g2s(SKV + s * 32768,         Kh + kv, 8192, full);
            bulk_g2s(SKV + s * 32768 + 8192,  Kl + kv, 8192, full);
            bulk_g2s(SKV + s * 32768 + 16384, Vh + kv, 8192, full);
            bulk_g2s(SKV + s * 32768 + 24576, Vl + kv, 8192, full);
        }
    }

    float o[8][4];
#pragma unroll
    for (int nt = 0; nt < 8; nt++)
#pragma unroll
        for (int r = 0; r < 4; r++) o[nt][r] = 0.0f;
    float mi[2] = {-1e30f, -1e30f};
    float li[2] = {0.0f, 0.0f};

    const int rsel = lane & 15;
    const int ksel = (lane >> 4) << 3;
    const int gr = lane >> 2;
    const int gc = lane & 3;
    const int qw = wid * 16;               // warp q-row offset in tile

    MBARRIER_WAIT_PARITY(QBAR, 0);

    for (int i = 0; i < T; i++) {
        const int st = i & 1;
        MBARRIER_WAIT_PARITY(FULLB + 8 * st, (i >> 1) & 1);
        const uint32_t Kb  = SKV + st * 32768;
        const uint32_t Klb = Kb + 8192;
        const uint32_t Vb  = Kb + 16384;
        const uint32_t Vlb = Kb + 24576;

        // ---- S = Q K^T (3-term split) ----
        float c[8][4];
#pragma unroll
        for (int nt = 0; nt < 8; nt++)
#pragma unroll
            for (int r = 0; r < 4; r++) c[nt][r] = 0.0f;

#pragma unroll
        for (int kc = 0; kc < 4; kc++) {
            const uint32_t kb = (uint32_t)((kc * 16 + ksel) * 2);
            const int qrow = qw + rsel;
            uint32_t aqh[4], aql[4];
            ldsm_x4(aqh, SQ + qrow * 128 + (kb ^ ((qrow & 7) << 4)));
            ldsm_x4(aql, SQ + 8192 + qrow * 128 + (kb ^ ((qrow & 7) << 4)));
#pragma unroll
            for (int ntp = 0; ntp < 4; ntp++) {
                const int krow = ntp * 16 + rsel;
                const uint32_t koff = kb ^ ((krow & 7) << 4);
                uint32_t kh4[4], kl4[4];
                ldsm_x4(kh4, Kb + krow * 128 + koff);
                ldsm_x4(kl4, Klb + krow * 128 + koff);
                mma_bf16(c[ntp * 2 + 0], aqh, kh4[0], kh4[2]);
                mma_bf16(c[ntp * 2 + 0], aql, kh4[0], kh4[2]);
                mma_bf16(c[ntp * 2 + 0], aqh, kl4[0], kl4[2]);
                mma_bf16(c[ntp * 2 + 1], aqh, kh4[1], kh4[3]);
                mma_bf16(c[ntp * 2 + 1], aql, kh4[1], kh4[3]);
                mma_bf16(c[ntp * 2 + 1], aqh, kl4[1], kl4[3]);
            }
        }

        // ---- causal mask ----
        const int kv0 = i * 64;
        const int row0 = q0 + qw + gr;
        if (kv0 + 63 > q0 + qw) {
#pragma unroll
            for (int nt = 0; nt < 8; nt++) {
                const int col = kv0 + nt * 8 + gc * 2;
                if (col     > row0)     c[nt][0] = -1e30f;
                if (col + 1 > row0)     c[nt][1] = -1e30f;
                if (col     > row0 + 8) c[nt][2] = -1e30f;
                if (col + 1 > row0 + 8) c[nt][3] = -1e30f;
            }
        }

        // ---- online softmax (2 rows per thread) ----
#pragma unroll
        for (int h2 = 0; h2 < 2; h2++) {
            float rm = -1e30f;
#pragma unroll
            for (int nt = 0; nt < 8; nt++)
                rm = fmaxf(rm, fmaxf(c[nt][h2 * 2], c[nt][h2 * 2 + 1]));
            rm = fmaxf(rm, __shfl_xor_sync(0xffffffffu, rm, 1));
            rm = fmaxf(rm, __shfl_xor_sync(0xffffffffu, rm, 2));
            const float mn = fmaxf(mi[h2], rm);
            const float corr = __expf(mi[h2] - mn);
            mi[h2] = mn;
            float rs = 0.0f;
#pragma unroll
            for (int nt = 0; nt < 8; nt++) {
                float p0 = __expf(c[nt][h2 * 2] - mn);
                float p1 = __expf(c[nt][h2 * 2 + 1] - mn);
                c[nt][h2 * 2] = p0; c[nt][h2 * 2 + 1] = p1;
                rs += p0 + p1;
            }
            rs += __shfl_xor_sync(0xffffffffu, rs, 1);
            rs += __shfl_xor_sync(0xffffffffu, rs, 2);
            li[h2] = li[h2] * corr + rs;
#pragma unroll
            for (int nt = 0; nt < 8; nt++) {
                o[nt][h2 * 2] *= corr; o[nt][h2 * 2 + 1] *= corr;
            }
        }

        // ---- O += P V (3-term split) ----
#pragma unroll
        for (int kc = 0; kc < 4; kc++) {
            uint32_t ph[4], pl[4];
            float r0, r1;
            ph[0] = split_hi(c[2 * kc][0], c[2 * kc][1], r0, r1);     pl[0] = pack_bf16(r0, r1);
            ph[1] = split_hi(c[2 * kc][2], c[2 * kc][3], r0, r1);     pl[1] = pack_bf16(r0, r1);
            ph[2] = split_hi(c[2 * kc + 1][0], c[2 * kc + 1][1], r0, r1); pl[2] = pack_bf16(r0, r1);
            ph[3] = split_hi(c[2 * kc + 1][2], c[2 * kc + 1][3], r0, r1); pl[3] = pack_bf16(r0, r1);

            const int krow = kc * 16 + rsel;
            const uint32_t swz = (uint32_t)((krow & 7) << 4);
#pragma unroll
            for (int ntd = 0; ntd < 4; ntd++) {
                const uint32_t cb = (uint32_t)((ntd * 16 + ksel) * 2);
                uint32_t vh4[4], vl4[4];
                ldsm_x4_t(vh4, Vb + krow * 128 + (cb ^ swz));
                ldsm_x4_t(vl4, Vlb + krow * 128 + (cb ^ swz));
                mma_bf16(o[ntd * 2 + 0], ph, vh4[0], vh4[1]);
                mma_bf16(o[ntd * 2 + 0], pl, vh4[0], vh4[1]);
                mma_bf16(o[ntd * 2 + 0], ph, vl4[0], vl4[1]);
                mma_bf16(o[ntd * 2 + 1], ph, vh4[2], vh4[3]);
                mma_bf16(o[ntd * 2 + 1], pl, vh4[2], vh4[3]);
                mma_bf16(o[ntd * 2 + 1], ph, vl4[2], vl4[3]);
            }
        }

        __syncthreads();
        if (tid == 0 && i + ATT_STAGES < T) {
            const int j = i + ATT_STAGES;
            const uint32_t full = FULLB + 8 * st;
            MBARRIER_EXPECT_TX(full, 32768);
            const size_t kv = headoff + (size_t)j * 4096;
            bulk_g2s(SKV + st * 32768,         Kh + kv, 8192, full);
            bulk_g2s(SKV + st * 32768 + 8192,  Kl + kv, 8192, full);
            bulk_g2s(SKV + st * 32768 + 16384, Vh + kv, 8192, full);
            bulk_g2s(SKV + st * 32768 + 24576, Vl + kv, 8192, full);
        }
    }

    // ---- normalize + store ctx as bf16 hi/lo chunks ----
    const float inv0 = 1.0f / li[0];
    const float inv1 = 1.0f / li[1];
    const int mrow0 = bb * SEQ + q0 + qw + gr;
#pragma unroll
    for (int nt = 0; nt < 8; nt++) {
        const int dcol = nt * 8 + gc * 2;
#pragma unroll
        for (int h2 = 0; h2 < 2; h2++) {
            const int m = mrow0 + h2 * 8;
            const float vx = o[nt][h2 * 2] * (h2 ? inv1 : inv0);
            const float vy = o[nt][h2 * 2 + 1] * (h2 ? inv1 : inv0);
            float lx, ly;
            uint32_t hp = split_hi(vx, vy, lx, ly);
            uint32_t lp = pack_bf16(lx, ly);
            const int rb = m >> 7;
            const int rr = m & 127;
            size_t blkbytes = ((size_t)(hh * MBTOT + rb)) * 16384;
            uint32_t off = (uint32_t)(rr * 128 + dcol * 2);
            off ^= (off >> 3) & 0x70;
            *(uint32_t*)((char*)g_ctx2hi + blkbytes + off) = hp;
            *(uint32_t*)((char*)g_ctx2lo + blkbytes + off) = lp;
        }
    }
}

// ---------------------------------------------------------------------------
// LayerNorm; optionally also writes bf16 hi/lo chunks (for h).
// ---------------------------------------------------------------------------
__global__ void __launch_bounds__(256) ln_kernel(
    const float* __restrict__ in, const float* __restrict__ sc,
    const float* __restrict__ bi, float* __restrict__ out,
    __nv_bfloat16* __restrict__ hi, __nv_bfloat16* __restrict__ lo)
{
    __shared__ float red0[8], red1[8];
    __shared__ float s_mu, s_inv;
    const int row = blockIdx.x;
    const int tid = threadIdx.x;

    float4 x = ((const float4*)(in + (size_t)row * DMODEL))[tid];
    float sum = x.x + x.y + x.z + x.w;
    float sq  = x.x * x.x + x.y * x.y + x.z * x.z + x.w * x.w;
#pragma unroll
    for (int o = 16; o; o >>= 1) {
        sum += __shfl_xor_sync(0xffffffffu, sum, o);
        sq  += __shfl_xor_sync(0xffffffffu, sq, o);
    }
    if ((tid & 31) == 0) { red0[tid >> 5] = sum; red1[tid >> 5] = sq; }
    __syncthreads();
    if (tid < 32) {
        float s = (tid < 8) ? red0[tid] : 0.0f;
        float q = (tid < 8) ? red1[tid] : 0.0f;
#pragma unroll
        for (int o = 4; o; o >>= 1) {
            s += __shfl_xor_sync(0xffffffffu, s, o);
            q += __shfl_xor_sync(0xffffffffu, q, o);
        }
        if (tid == 0) {
            float mu = s * (1.0f / DMODEL);
            float var = q * (1.0f / DMODEL) - mu * mu;
            s_mu = mu;
            s_inv = rsqrtf(var + 1e-5f);
        }
    }
    __syncthreads();
    const float mu = s_mu, inv = s_inv;
    float4 g = ((const float4*)sc)[tid];
    float4 b = ((const float4*)bi)[tid];
    float4 o;
    o.x = (x.x - mu) * inv * g.x + b.x;
    o.y = (x.y - mu) * inv * g.y + b.y;
    o.z = (x.z - mu) * inv * g.z + b.z;
    o.w = (x.w - mu) * inv * g.w + b.w;
    ((float4*)(out + (size_t)row * DMODEL))[tid] = o;

    if (hi) {
        float l0, l1, l2, l3;
        uint32_t h01 = split_hi(o.x, o.y, l0, l1);
        uint32_t h23 = split_hi(o.z, o.w, l2, l3);
        const int col = tid * 4;
        const int kc = col >> 6;
        const int c = col & 63;
        const int rb = row >> 7;
        const int rr = row & 127;
        size_t blkbytes = ((size_t)(kc * MBTOT + rb)) * 16384;
        uint32_t off = (uint32_t)(rr * 128 + c * 2);
        off ^= (off >> 3) & 0x70;
        uint2 hu, lu;
        hu.x = h01; hu.y = h23;
        lu.x = pack_bf16(l0, l1); lu.y = pack_bf16(l2, l3);
        *reinterpret_cast<uint2*>((char*)hi + blkbytes + off) = hu;
        *reinterpret_cast<uint2*>((char*)lo + blkbytes + off) = lu;
    }
}

// ---------------------------------------------------------------------------
extern "C" void kernel_launch(void* const* d_in, const int* in_sizes, int n_in,
                              void* d_out, int out_size)
{
    (void)in_sizes; (void)n_in; (void)out_size;
    const float* x    = (const float*)d_in[0];
    const float* wq   = (const float*)d_in[2];
    const float* bq   = (const float*)d_in[3];
    const float* wk   = (const float*)d_in[4];
    const float* bk   = (const float*)d_in[5];
    const float* wv   = (const float*)d_in[6];
    const float* bv   = (const float*)d_in[7];
    const float* wo   = (const float*)d_in[8];
    const float* bo   = (const float*)d_in[9];
    const float* w1   = (const float*)d_in[10];
    const float* b1   = (const float*)d_in[11];
    const float* w2   = (const float*)d_in[12];
    const float* b2   = (const float*)d_in[13];
    const float* ln1s = (const float*)d_in[14];
    const float* ln1b = (const float*)d_in[15];
    const float* ln2s = (const float*)d_in[16];
    const float* ln2b = (const float*)d_in[17];
    float* out = (float*)d_out;

    float *res1, *h, *res2, *bqkv;
    cudaGetSymbolAddress((void**)&res1, g_res1);
    cudaGetSymbolAddress((void**)&h,    g_h);
    cudaGetSymbolAddress((void**)&res2, g_res2);
    cudaGetSymbolAddress((void**)&bqkv, g_bqkv);

    __nv_bfloat16 *x2h, *x2l, *c2h, *c2l, *h2h, *h2l, *f2h, *f2l;
    __nv_bfloat16 *wqkvh, *wqkvl, *woh, *wol, *w1h, *w1l, *w2h, *w2l;
    __nv_bfloat16 *qh, *ql, *kh, *kl, *vh, *vl;
    cudaGetSymbolAddress((void**)&x2h, g_x2hi);   cudaGetSymbolAddress((void**)&x2l, g_x2lo);
    cudaGetSymbolAddress((void**)&c2h, g_ctx2hi); cudaGetSymbolAddress((void**)&c2l, g_ctx2lo);
    cudaGetSymbolAddress((void**)&h2h, g_h2hi);   cudaGetSymbolAddress((void**)&h2l, g_h2lo);
    cudaGetSymbolAddress((void**)&f2h, g_ff2hi);  cudaGetSymbolAddress((void**)&f2l, g_ff2lo);
    cudaGetSymbolAddress((void**)&wqkvh, g_wqkvhi); cudaGetSymbolAddress((void**)&wqkvl, g_wqkvlo);
    cudaGetSymbolAddress((void**)&woh, g_wohi);   cudaGetSymbolAddress((void**)&wol, g_wolo);
    cudaGetSymbolAddress((void**)&w1h, g_w1hi);   cudaGetSymbolAddress((void**)&w1l, g_w1lo);
    cudaGetSymbolAddress((void**)&w2h, g_w2hi);   cudaGetSymbolAddress((void**)&w2l, g_w2lo);
    cudaGetSymbolAddress((void**)&qh, g_Qh); cudaGetSymbolAddress((void**)&ql, g_Ql);
    cudaGetSymbolAddress((void**)&kh, g_Kh); cudaGetSymbolAddress((void**)&kl, g_Kl);
    cudaGetSymbolAddress((void**)&vh, g_Vh); cudaGetSymbolAddress((void**)&vl, g_Vl);

    cudaFuncSetAttribute(tc_gemm<0>, cudaFuncAttributeMaxDynamicSharedMemorySize, GEMM_SMEM_BYTES);
    cudaFuncSetAttribute(tc_gemm<1>, cudaFuncAttributeMaxDynamicSharedMemorySize, GEMM_SMEM_BYTES);
    cudaFuncSetAttribute(tc_gemm<2>, cudaFuncAttributeMaxDynamicSharedMemorySize, GEMM_SMEM_BYTES);
    cudaFuncSetAttribute(attn_mma_kernel, cudaFuncAttributeMaxDynamicSharedMemorySize, ATT_SMEM);

    const dim3 blk256(256);

    // --- input + weight conversions ---
    convert_kernel<<<MROWS * DMODEL / 1024, blk256>>>(x,  x2h, x2l, DMODEL, MBTOT, 0);
    convert_kernel<<<DMODEL * DMODEL / 1024, blk256>>>(wq, wqkvh, wqkvl, DMODEL, 24, 0);
    convert_kernel<<<DMODEL * DMODEL / 1024, blk256>>>(wk, wqkvh, wqkvl, DMODEL, 24, 8);
    convert_kernel<<<DMODEL * DMODEL / 1024, blk256>>>(wv, wqkvh, wqkvl, DMODEL, 24, 16);
    convert_kernel<<<DMODEL * DMODEL / 1024, blk256>>>(wo, woh, wol, DMODEL, 8, 0);
    convert_kernel<<<DFF * DMODEL / 1024, blk256>>>(w1, w1h, w1l, DMODEL, 32, 0);
    convert_kernel<<<DMODEL * DFF / 1024, blk256>>>(w2, w2h, w2l, DFF, 8, 0);
    concat_bias_kernel<<<12, blk256>>>(bq, bk, bv);

    // --- QKV fused GEMM -> bf16 hi/lo per-head tiles ---
    tc_gemm<0><<<dim3(24, MBTOT), blk256, GEMM_SMEM_BYTES>>>(
        x2h, x2l, wqkvh, wqkvl, DMODEL / 64, MBTOT, 24, bqkv, nullptr, nullptr, 3072);

    // --- HMMA flash attention -> ctx bf16 hi/lo chunks ---
    attn_mma_kernel<<<dim3(SEQ / 64, NHEAD, BATCH), 128, ATT_SMEM>>>(qh, ql, kh, kl, vh, vl);

    // --- O projection + residual(x) -> res1; LN1 -> h (fp32 + bf16 chunks) ---
    tc_gemm<1><<<dim3(8, MBTOT), blk256, GEMM_SMEM_BYTES>>>(
        c2h, c2l, woh, wol, DMODEL / 64, MBTOT, 8, bo, x, res1, DMODEL);
    ln_kernel<<<MROWS, blk256>>>(res1, ln1s, ln1b, h, h2h, h2l);

    // --- FFN1 + GELU -> ff bf16 hi/lo chunks directly ---
    tc_gemm<2><<<dim3(32, MBTOT), blk256, GEMM_SMEM_BYTES>>>(
        h2h, h2l, w1h, w1l, DMODEL / 64, MBTOT, 32, b1, nullptr, nullptr, DFF);

    // --- FFN2 + residual(h) -> res2; LN2 -> out ---
    tc_gemm<1><<<dim3(8, MBTOT), blk256, GEMM_SMEM_BYTES>>>(
        f2h, f2l, w2h, w2l, DFF / 64, MBTOT, 8, b2, h, res2, DMODEL);
    ln_kernel<<<MROWS, blk256>>>(res2, ln2s, ln2b, out, nullptr, nullptr);
}